// round 8
// baseline (speedup 1.0000x reference)
#include <cuda_runtime.h>
#include <math.h>

#define N_NODES 100000
#define N_EDGES 1000000
#define F_DIM   128
#define ED_DIM  16
#define HC      80

// ---------------- scratch (static device globals; no runtime alloc) ----------------
__device__ float g_xl[N_NODES * HC];
__device__ float g_xr[N_NODES * HC];
__device__ float g_h [N_NODES * HC];
__device__ float g_s [N_NODES * 5];       // per-node per-head softmax denominators
__device__ int   g_counts[N_NODES];
__device__ int   g_whead [N_NODES];
__device__ int   g_done;
__device__ int   g_csr_src[N_EDGES];
__device__ int   g_csr_dst[N_EDGES];
__device__ float g_eattr_csr[N_EDGES * ED_DIM];   // eattr in CSR slot order

// ---------------- fused hist + exclusive scan (last block scans) ----------------
__global__ void __launch_bounds__(1024) k_histscan(const int* __restrict__ dst) {
    int e = blockIdx.x * 1024 + threadIdx.x;
    if (e < N_EDGES) atomicAdd(&g_counts[__ldcs(&dst[e])], 1);
    __threadfence();
    __shared__ int islast;
    __syncthreads();
    if (threadIdx.x == 0) {
        int t = atomicAdd(&g_done, 1);
        islast = (t == (int)gridDim.x - 1);
    }
    __syncthreads();
    if (!islast) return;

    // exclusive scan of counts -> g_whead (scatter cursors)
    __shared__ int ssum[1024];
    int tid = threadIdx.x;
    const int per = (N_NODES + 1023) / 1024;
    int base = tid * per;
    int end = base + per; if (end > N_NODES) end = N_NODES;
    int s = 0;
    for (int i = base; i < end; i++) s += g_counts[i];
    ssum[tid] = s;
    __syncthreads();
    for (int d = 1; d < 1024; d <<= 1) {
        int v = (tid >= d) ? ssum[tid - d] : 0;
        __syncthreads();
        ssum[tid] += v;
        __syncthreads();
    }
    int run = (tid > 0) ? ssum[tid - 1] : 0;
    for (int i = base; i < end; i++) {
        g_whead[i] = run;
        run += g_counts[i];
    }
}

// Scatter: csr_src, csr_dst, eattr re-ordered into CSR (dst-sorted) slot order.
__global__ void k_scatter(const int* __restrict__ src, const int* __restrict__ dst,
                          const float* __restrict__ eattr) {
    int e = blockIdx.x * blockDim.x + threadIdx.x;
    if (e < N_EDGES) {
        int d = __ldcs(&dst[e]);
        int p = atomicAdd(&g_whead[d], 1);
        g_csr_src[p] = __ldcs(&src[e]);
        g_csr_dst[p] = d;
        const float4* i4 = reinterpret_cast<const float4*>(eattr) + (size_t)e * 4;
        float4* o4 = reinterpret_cast<float4*>(g_eattr_csr) + (size_t)p * 4;
        float4 v0 = __ldcs(i4 + 0), v1 = __ldcs(i4 + 1);
        float4 v2 = __ldcs(i4 + 2), v3 = __ldcs(i4 + 3);
        __stcs(o4 + 0, v0); __stcs(o4 + 1, v1);
        __stcs(o4 + 2, v2); __stcs(o4 + 3, v3);
    }
}

// ---------------- fused xl/xr GEMM (unchanged) ----------------
__global__ void __launch_bounds__(256) k_gemm(const float* __restrict__ in, int din,
                                              const float* __restrict__ wl, const float* __restrict__ bl,
                                              const float* __restrict__ wr, const float* __restrict__ br) {
    __shared__ float inp_sm[32][65];
    __shared__ float w_sm[32][161];
    int row0 = blockIdx.x * 64;
    int tid = threadIdx.x;
    int ty = tid >> 5;
    int tx = tid & 31;
    float acc[8][5];
#pragma unroll
    for (int r = 0; r < 8; r++)
#pragma unroll
        for (int c = 0; c < 5; c++) acc[r][c] = 0.f;

    for (int kk = 0; kk < din; kk += 32) {
        int kc = din - kk; if (kc > 32) kc = 32;
        for (int i = tid; i < 64 * 32; i += 256) {
            int k = i & 31, r = i >> 5;
            float v = 0.f;
            int row = row0 + r;
            if (k < kc && row < N_NODES) v = __ldcs(&in[row * din + kk + k]);
            inp_sm[k][r] = v;
        }
        for (int i = tid; i < 160 * 32; i += 256) {
            int k = i & 31, c = i >> 5;
            float v = 0.f;
            if (k < kc) v = (c < 80) ? wl[c * din + kk + k] : wr[(c - 80) * din + kk + k];
            w_sm[k][c] = v;
        }
        __syncthreads();
#pragma unroll 8
        for (int k = 0; k < 32; k++) {
            float a[8], b[5];
#pragma unroll
            for (int r = 0; r < 8; r++) a[r] = inp_sm[k][ty * 8 + r];
#pragma unroll
            for (int c = 0; c < 5; c++) b[c] = w_sm[k][tx + 32 * c];
#pragma unroll
            for (int r = 0; r < 8; r++)
#pragma unroll
                for (int c = 0; c < 5; c++) acc[r][c] = fmaf(a[r], b[c], acc[r][c]);
        }
        __syncthreads();
    }
#pragma unroll
    for (int r = 0; r < 8; r++) {
        int row = row0 + ty * 8 + r;
        if (row < N_NODES) {
#pragma unroll
            for (int c = 0; c < 5; c++) {
                int col = tx + 32 * c;
                if (col < 80) g_xl[row * HC + col] = acc[r][c] + bl[col];
                else          __stcs(&g_xr[row * HC + (col - 80)], acc[r][c] + br[col - 80]);
            }
        }
    }
}

// ---------------- fused attention + aggregation (edge-parallel, run-flush atomics) ----
// One warp per 32 consecutive CSR slots (dst-sorted). Computes per-edge per-head
// exp-weights AND accumulates w, w*xl per dst-run in registers; flushes each run
// with atomicAdd (out += acc, g_s += s). k_aggr is gone; xl never re-gathered.
__global__ void __launch_bounds__(256, 2) k_alpha(const float* __restrict__ we,
                                                  const float* __restrict__ att,
                                                  float* __restrict__ out) {
    int warp = threadIdx.x >> 5;
    int lane = threadIdx.x & 31;
    int base = (blockIdx.x * 8 + warp) * 32;
    if (base >= N_EDGES) return;
    int cnt = N_EDGES - base; if (cnt > 32) cnt = 32;

    int ch0 = lane, ch1 = lane + 32, ch2 = lane + 64;
    bool has2 = lane < 16;
    int ch2c = has2 ? ch2 : 64;

    float w0[16], w1[16], w2[16];
#pragma unroll
    for (int j = 0; j < 16; j++) {
        w0[j] = __ldg(&we[ch0 * 16 + j]);
        w1[j] = __ldg(&we[ch1 * 16 + j]);
        w2[j] = __ldg(&we[ch2c * 16 + j]);
    }
    float a0 = __ldg(&att[ch0]), a1 = __ldg(&att[ch1]), a2 = __ldg(&att[ch2c]);

    int sv = 0, dv = 0;
    if (lane < cnt) {
        sv = __ldcs(&g_csr_src[base + lane]);
        dv = __ldcs(&g_csr_dst[base + lane]);
    }

    // prefetch edge 0
    int dcur = __shfl_sync(0xffffffffu, dv, 0);
    int scur = __shfl_sync(0xffffffffu, sv, 0);
    const float* xp = g_xl + (size_t)scur * HC;
    const float* rp = g_xr + (size_t)dcur * HC;
    float nx0 = xp[ch0], nx1 = xp[ch1], nx2 = has2 ? xp[ch2] : 0.f;
    float nr0 = rp[ch0], nr1 = rp[ch1], nr2 = has2 ? rp[ch2] : 0.f;
    const float4* eap = reinterpret_cast<const float4*>(g_eattr_csr) + (size_t)base * 4;
    float4 ne0 = __ldcs(eap + 0), ne1 = __ldcs(eap + 1);
    float4 ne2 = __ldcs(eap + 2), ne3 = __ldcs(eap + 3);

    float acc0 = 0.f, acc1 = 0.f, acc2 = 0.f;
    float ss0 = 0.f, ss1 = 0.f, ss2 = 0.f;

    for (int j = 0; j < cnt; j++) {
        float xs0 = nx0, xs1 = nx1, xs2 = nx2;
        float xr0 = nr0, xr1 = nr1, xr2 = nr2;
        float4 f0 = ne0, f1 = ne1, f2 = ne2, f3 = ne3;

        int dnext = -1;
        if (j + 1 < cnt) {
            int sn = __shfl_sync(0xffffffffu, sv, j + 1);
            dnext  = __shfl_sync(0xffffffffu, dv, j + 1);
            const float* xpn = g_xl + (size_t)sn * HC;
            const float* rpn = g_xr + (size_t)dnext * HC;
            nx0 = xpn[ch0]; nx1 = xpn[ch1]; nx2 = has2 ? xpn[ch2] : 0.f;
            nr0 = rpn[ch0]; nr1 = rpn[ch1]; nr2 = has2 ? rpn[ch2] : 0.f;
            const float4* ean = reinterpret_cast<const float4*>(g_eattr_csr) + (size_t)(base + j + 1) * 4;
            ne0 = __ldcs(ean + 0); ne1 = __ldcs(ean + 1);
            ne2 = __ldcs(ean + 2); ne3 = __ldcs(ean + 3);
        }

        float ea[16] = { f0.x, f0.y, f0.z, f0.w, f1.x, f1.y, f1.z, f1.w,
                         f2.x, f2.y, f2.z, f2.w, f3.x, f3.y, f3.z, f3.w };
        float em0 = 0.f, em1 = 0.f, em2 = 0.f;
#pragma unroll
        for (int t = 0; t < 16; t++) {
            em0 = fmaf(w0[t], ea[t], em0);
            em1 = fmaf(w1[t], ea[t], em1);
            em2 = fmaf(w2[t], ea[t], em2);
        }

        float m0 = xs0 + xr0 + em0; m0 = (m0 > 0.f) ? m0 : 0.2f * m0;
        float m1 = xs1 + xr1 + em1; m1 = (m1 > 0.f) ? m1 : 0.2f * m1;
        float m2 = xs2 + xr2 + em2; m2 = (m2 > 0.f) ? m2 : 0.2f * m2;

        float p0 = m0 * a0, p1 = m1 * a1, p2 = m2 * a2;
#pragma unroll
        for (int off = 8; off > 0; off >>= 1) {
            p0 += __shfl_xor_sync(0xffffffffu, p0, off);
            p1 += __shfl_xor_sync(0xffffffffu, p1, off);
            p2 += __shfl_xor_sync(0xffffffffu, p2, off);
        }

        float e0w = __expf(p0), e1w = __expf(p1), e2w = __expf(p2);
        ss0 += e0w; acc0 = fmaf(e0w, xs0, acc0);
        ss1 += e1w; acc1 = fmaf(e1w, xs1, acc1);
        ss2 += e2w; acc2 = fmaf(e2w, xs2, acc2);

        // flush this dst-run when the next edge targets a different node (or chunk ends)
        bool flush = (j + 1 >= cnt) || (dnext != dcur);
        if (flush) {
            float* op = out + (size_t)dcur * HC;
            atomicAdd(&op[ch0], acc0);
            atomicAdd(&op[ch1], acc1);
            if (has2) atomicAdd(&op[ch2], acc2);
            if (lane == 0) {
                atomicAdd(&g_s[dcur * 5 + 0], ss0);
                atomicAdd(&g_s[dcur * 5 + 2], ss1);
                atomicAdd(&g_s[dcur * 5 + 4], ss2);
            } else if (lane == 16) {
                atomicAdd(&g_s[dcur * 5 + 1], ss0);
                atomicAdd(&g_s[dcur * 5 + 3], ss1);
            }
            acc0 = acc1 = acc2 = 0.f;
            ss0 = ss1 = ss2 = 0.f;
        }
        dcur = dnext;
    }
}

// ---------------- normalize: out = acc/s + bias (+relu) ----------------
__global__ void k_norm(const float* __restrict__ bias, float* __restrict__ out, int applyRelu) {
    int id = blockIdx.x * blockDim.x + threadIdx.x;
    if (id >= N_NODES * HC) return;
    int n = id / HC, c = id - n * HC;
    float s = g_s[n * 5 + (c >> 4)];
    float v = out[id] / (s + 1e-16f) + __ldg(&bias[c]);
    if (applyRelu) v = fmaxf(v, 0.f);
    out[id] = v;
}

// ---------------- launch ----------------
extern "C" void kernel_launch(void* const* d_in, const int* in_sizes, int n_in,
                              void* d_out, int out_size) {
    const float* x     = (const float*)d_in[0];
    const int*   ei    = (const int*)d_in[1];
    const float* eattr = (const float*)d_in[2];
    const float* W[21];
    for (int i = 0; i < 21; i++) W[i] = (const float*)d_in[3 + i];

    const int* src = ei;
    const int* dst = ei + N_EDGES;

    float* hbuf = nullptr;  cudaGetSymbolAddress((void**)&hbuf, g_h);
    float* sbuf = nullptr;  cudaGetSymbolAddress((void**)&sbuf, g_s);
    int* counts_ptr = nullptr; cudaGetSymbolAddress((void**)&counts_ptr, g_counts);
    int* done_ptr = nullptr;   cudaGetSymbolAddress((void**)&done_ptr, g_done);

    cudaMemsetAsync(counts_ptr, 0, N_NODES * sizeof(int));
    cudaMemsetAsync(done_ptr, 0, sizeof(int));

    // kernel launch order (ncu captures launch #3): histscan(0), scatter(1), gemm(2), alpha(3)
    k_histscan<<<(N_EDGES + 1023) / 1024, 1024>>>(dst);
    k_scatter <<<(N_EDGES + 255) / 256, 256>>>(src, dst, eattr);

    const float* inp = x;
    int din = F_DIM;
    for (int L = 0; L < 3; L++) {
        const float* wl   = W[L * 7 + 0];
        const float* bl   = W[L * 7 + 1];
        const float* wr   = W[L * 7 + 2];
        const float* br   = W[L * 7 + 3];
        const float* we   = W[L * 7 + 4];
        const float* att  = W[L * 7 + 5];
        const float* bias = W[L * 7 + 6];

        k_gemm<<<(N_NODES + 63) / 64, 256>>>(inp, din, wl, bl, wr, br);

        float* outp = (L == 2) ? (float*)d_out : hbuf;
        cudaMemsetAsync(outp, 0, N_NODES * HC * sizeof(float));
        cudaMemsetAsync(sbuf, 0, N_NODES * 5 * sizeof(float));

        k_alpha<<<(N_EDGES / 32 + 7) / 8, 256>>>(we, att, outp);
        k_norm <<<(N_NODES * HC + 255) / 256, 256>>>(bias, outp, (L < 2) ? 1 : 0);

        inp = hbuf;
        din = HC;
    }
}

// round 9
// speedup vs baseline: 1.1757x; 1.1757x over previous
#include <cuda_runtime.h>
#include <math.h>

#define N_NODES 100000
#define N_EDGES 1000000
#define F_DIM   128
#define ED_DIM  16
#define HC      80

// ---------------- scratch (static device globals; no runtime alloc) ----------------
__device__ float g_xl[N_NODES * HC];
__device__ float g_xr[N_NODES * HC];
__device__ float g_h [N_NODES * HC];
__device__ int   g_counts[N_NODES];
__device__ int   g_rowptr[N_NODES + 1];
__device__ int   g_whead [N_NODES];
__device__ int   g_done;
__device__ int   g_csr_src[N_EDGES];
__device__ int   g_csr_dst[N_EDGES];
__device__ float g_eattr_csr[N_EDGES * ED_DIM];   // eattr in CSR slot order
__device__ float g_w[N_EDGES * 5];                // per-edge per-head exp weights (CSR order)

// ---------------- fused hist + exclusive scan (last block scans) ----------------
__global__ void __launch_bounds__(1024) k_histscan(const int* __restrict__ dst) {
    int e = blockIdx.x * 1024 + threadIdx.x;
    if (e < N_EDGES) atomicAdd(&g_counts[__ldcs(&dst[e])], 1);
    __threadfence();
    __shared__ int islast;
    __syncthreads();
    if (threadIdx.x == 0) {
        int t = atomicAdd(&g_done, 1);
        islast = (t == (int)gridDim.x - 1);
    }
    __syncthreads();
    if (!islast) return;

    __shared__ int ssum[1024];
    int tid = threadIdx.x;
    const int per = (N_NODES + 1023) / 1024;
    int base = tid * per;
    int end = base + per; if (end > N_NODES) end = N_NODES;
    int s = 0;
    for (int i = base; i < end; i++) s += g_counts[i];
    ssum[tid] = s;
    __syncthreads();
    for (int d = 1; d < 1024; d <<= 1) {
        int v = (tid >= d) ? ssum[tid - d] : 0;
        __syncthreads();
        ssum[tid] += v;
        __syncthreads();
    }
    int run = (tid > 0) ? ssum[tid - 1] : 0;
    for (int i = base; i < end; i++) {
        g_rowptr[i] = run;
        g_whead[i] = run;
        run += g_counts[i];
    }
    if (tid == 0) g_rowptr[N_NODES] = N_EDGES;
}

// Scatter: csr_src, csr_dst, eattr re-ordered into CSR (dst-sorted) slot order.
__global__ void k_scatter(const int* __restrict__ src, const int* __restrict__ dst,
                          const float* __restrict__ eattr) {
    int e = blockIdx.x * blockDim.x + threadIdx.x;
    if (e < N_EDGES) {
        int d = __ldcs(&dst[e]);
        int p = atomicAdd(&g_whead[d], 1);
        g_csr_src[p] = __ldcs(&src[e]);
        g_csr_dst[p] = d;
        const float4* i4 = reinterpret_cast<const float4*>(eattr) + (size_t)e * 4;
        float4* o4 = reinterpret_cast<float4*>(g_eattr_csr) + (size_t)p * 4;
        float4 v0 = __ldcs(i4 + 0), v1 = __ldcs(i4 + 1);
        float4 v2 = __ldcs(i4 + 2), v3 = __ldcs(i4 + 3);
        __stcs(o4 + 0, v0); __stcs(o4 + 1, v1);
        __stcs(o4 + 2, v2); __stcs(o4 + 3, v3);
    }
}

// ---------------- fused xl/xr GEMM (unchanged) ----------------
__global__ void __launch_bounds__(256) k_gemm(const float* __restrict__ in, int din,
                                              const float* __restrict__ wl, const float* __restrict__ bl,
                                              const float* __restrict__ wr, const float* __restrict__ br) {
    __shared__ float inp_sm[32][65];
    __shared__ float w_sm[32][161];
    int row0 = blockIdx.x * 64;
    int tid = threadIdx.x;
    int ty = tid >> 5;
    int tx = tid & 31;
    float acc[8][5];
#pragma unroll
    for (int r = 0; r < 8; r++)
#pragma unroll
        for (int c = 0; c < 5; c++) acc[r][c] = 0.f;

    for (int kk = 0; kk < din; kk += 32) {
        int kc = din - kk; if (kc > 32) kc = 32;
        for (int i = tid; i < 64 * 32; i += 256) {
            int k = i & 31, r = i >> 5;
            float v = 0.f;
            int row = row0 + r;
            if (k < kc && row < N_NODES) v = __ldcs(&in[row * din + kk + k]);
            inp_sm[k][r] = v;
        }
        for (int i = tid; i < 160 * 32; i += 256) {
            int k = i & 31, c = i >> 5;
            float v = 0.f;
            if (k < kc) v = (c < 80) ? wl[c * din + kk + k] : wr[(c - 80) * din + kk + k];
            w_sm[k][c] = v;
        }
        __syncthreads();
#pragma unroll 8
        for (int k = 0; k < 32; k++) {
            float a[8], b[5];
#pragma unroll
            for (int r = 0; r < 8; r++) a[r] = inp_sm[k][ty * 8 + r];
#pragma unroll
            for (int c = 0; c < 5; c++) b[c] = w_sm[k][tx + 32 * c];
#pragma unroll
            for (int r = 0; r < 8; r++)
#pragma unroll
                for (int c = 0; c < 5; c++) acc[r][c] = fmaf(a[r], b[c], acc[r][c]);
        }
        __syncthreads();
    }
#pragma unroll
    for (int r = 0; r < 8; r++) {
        int row = row0 + ty * 8 + r;
        if (row < N_NODES) {
#pragma unroll
            for (int c = 0; c < 5; c++) {
                int col = tx + 32 * c;
                if (col < 80) g_xl[row * HC + col] = acc[r][c] + bl[col];
                else          __stcs(&g_xr[row * HC + (col - 80)], acc[r][c] + br[col - 80]);
            }
        }
    }
}

// ---------------- phase 1: edge-parallel attention weights (register-lean) ----------
// One warp per 32 consecutive CSR slots (dst-sorted). No double-buffering: loads
// issued at iteration top, overlapped by the scoreboard with the 48-FMA em block.
// xr reloaded only at dst-run boundaries (warp-uniform). Target: no spills.
__global__ void __launch_bounds__(256, 2) k_alpha(const float* __restrict__ we,
                                                  const float* __restrict__ att) {
    __shared__ float wsm[8][160];
    int warp = threadIdx.x >> 5;
    int lane = threadIdx.x & 31;
    int base = (blockIdx.x * 8 + warp) * 32;
    if (base >= N_EDGES) return;
    int cnt = N_EDGES - base; if (cnt > 32) cnt = 32;

    int ch0 = lane, ch1 = lane + 32, ch2 = lane + 64;
    bool has2 = lane < 16;
    int ch2c = has2 ? ch2 : 64;

    float w0[16], w1[16], w2[16];
#pragma unroll
    for (int j = 0; j < 16; j++) {
        w0[j] = __ldg(&we[ch0 * 16 + j]);
        w1[j] = __ldg(&we[ch1 * 16 + j]);
        w2[j] = __ldg(&we[ch2c * 16 + j]);
    }
    float a0 = __ldg(&att[ch0]), a1 = __ldg(&att[ch1]), a2 = __ldg(&att[ch2c]);

    int sv = 0, dv = 0;
    if (lane < cnt) {
        sv = __ldcs(&g_csr_src[base + lane]);
        dv = __ldcs(&g_csr_dst[base + lane]);
    }

    float xr0 = 0.f, xr1 = 0.f, xr2 = 0.f;
    int dlast = -1;

    for (int j = 0; j < cnt; j++) {
        int scur = __shfl_sync(0xffffffffu, sv, j);
        int dcur = __shfl_sync(0xffffffffu, dv, j);

        // issue all loads up front; consumed after the FMA block below
        const float4* eap = reinterpret_cast<const float4*>(g_eattr_csr) + (size_t)(base + j) * 4;
        float4 f0 = __ldcs(eap + 0), f1 = __ldcs(eap + 1);
        float4 f2 = __ldcs(eap + 2), f3 = __ldcs(eap + 3);
        const float* xp = g_xl + (size_t)scur * HC;
        float xs0 = xp[ch0];
        float xs1 = xp[ch1];
        float xs2 = has2 ? xp[ch2] : 0.f;

        if (dcur != dlast) {               // warp-uniform; ~1 in 3 edges
            const float* rp = g_xr + (size_t)dcur * HC;
            xr0 = rp[ch0];
            xr1 = rp[ch1];
            xr2 = has2 ? rp[ch2] : 0.f;
            dlast = dcur;
        }

        float em0 = 0.f, em1 = 0.f, em2 = 0.f;
        {
            float ea[16] = { f0.x, f0.y, f0.z, f0.w, f1.x, f1.y, f1.z, f1.w,
                             f2.x, f2.y, f2.z, f2.w, f3.x, f3.y, f3.z, f3.w };
#pragma unroll
            for (int t = 0; t < 16; t++) {
                em0 = fmaf(w0[t], ea[t], em0);
                em1 = fmaf(w1[t], ea[t], em1);
                em2 = fmaf(w2[t], ea[t], em2);
            }
        }

        float m0 = xs0 + xr0 + em0; m0 = (m0 > 0.f) ? m0 : 0.2f * m0;
        float m1 = xs1 + xr1 + em1; m1 = (m1 > 0.f) ? m1 : 0.2f * m1;
        float m2 = xs2 + xr2 + em2; m2 = (m2 > 0.f) ? m2 : 0.2f * m2;

        float p0 = m0 * a0, p1 = m1 * a1, p2 = m2 * a2;
#pragma unroll
        for (int off = 8; off > 0; off >>= 1) {
            p0 += __shfl_xor_sync(0xffffffffu, p0, off);
            p1 += __shfl_xor_sync(0xffffffffu, p1, off);
            p2 += __shfl_xor_sync(0xffffffffu, p2, off);
        }

        float e0w = __expf(p0), e1w = __expf(p1), e2w = __expf(p2);
        // lanes 0/16 hold the two 16-group head sums: heads {0,2,4} / {1,3}
        if (lane == 0) {
            wsm[warp][j * 5 + 0] = e0w;
            wsm[warp][j * 5 + 2] = e1w;
            wsm[warp][j * 5 + 4] = e2w;
        } else if (lane == 16) {
            wsm[warp][j * 5 + 1] = e0w;
            wsm[warp][j * 5 + 3] = e1w;
        }
    }
    __syncwarp();
    for (int i = lane; i < cnt * 5; i += 32)
        __stcs(&g_w[(size_t)base * 5 + i], wsm[warp][i]);
}

// ---------------- phase 2: per-node weighted aggregation ----------------
__global__ void __launch_bounds__(256) k_aggr(const float* __restrict__ bias,
                                              float* __restrict__ out, int applyRelu) {
    int warp = threadIdx.x >> 5;
    int lane = threadIdx.x & 31;
    int n = blockIdx.x * 8 + warp;
    if (n >= N_NODES) return;

    int ch0 = lane, ch1 = lane + 32, ch2 = lane + 64;
    bool has2 = lane < 16;
    int ch2c = has2 ? ch2 : 64;
    int hsel = lane >> 4;

    float s0 = 0.f, s1 = 0.f, s2 = 0.f;
    float acc0 = 0.f, acc1 = 0.f, acc2 = 0.f;

    int kb = g_rowptr[n], ke = g_rowptr[n + 1];
    for (int cb = kb; cb < ke; cb += 32) {
        int cnt = ke - cb; if (cnt > 32) cnt = 32;
        int sv = 0;
        if (lane < cnt) sv = __ldcs(&g_csr_src[cb + lane]);

        int src0 = __shfl_sync(0xffffffffu, sv, 0);
        const float* xp = g_xl + (size_t)src0 * HC;
        float nx0 = xp[ch0], nx1 = xp[ch1], nx2 = has2 ? xp[ch2] : 0.f;
        const float* wp = g_w + (size_t)cb * 5;
        float nw0 = __ldcs(&wp[hsel]);
        float nw1 = __ldcs(&wp[2 + hsel]);
        float nw2 = __ldcs(&wp[4]);

        for (int j = 0; j < cnt; j++) {
            float xs0 = nx0, xs1 = nx1, xs2 = nx2;
            float wv0 = nw0, wv1 = nw1, wv2 = nw2;
            if (j + 1 < cnt) {
                int sn = __shfl_sync(0xffffffffu, sv, j + 1);
                const float* xpn = g_xl + (size_t)sn * HC;
                nx0 = xpn[ch0]; nx1 = xpn[ch1]; nx2 = has2 ? xpn[ch2] : 0.f;
                const float* wpn = g_w + (size_t)(cb + j + 1) * 5;
                nw0 = __ldcs(&wpn[hsel]);
                nw1 = __ldcs(&wpn[2 + hsel]);
                nw2 = __ldcs(&wpn[4]);
            }
            s0 += wv0; acc0 = fmaf(wv0, xs0, acc0);
            s1 += wv1; acc1 = fmaf(wv1, xs1, acc1);
            s2 += wv2; acc2 = fmaf(wv2, xs2, acc2);
        }
    }

    float o0 = acc0 / (s0 + 1e-16f) + __ldg(&bias[ch0]);
    float o1 = acc1 / (s1 + 1e-16f) + __ldg(&bias[ch1]);
    float o2 = acc2 / (s2 + 1e-16f) + __ldg(&bias[ch2c]);
    if (applyRelu) {
        out[n * HC + ch0] = fmaxf(o0, 0.f);
        out[n * HC + ch1] = fmaxf(o1, 0.f);
        if (has2) out[n * HC + ch2] = fmaxf(o2, 0.f);
    } else {
        __stcs(&out[n * HC + ch0], o0);
        __stcs(&out[n * HC + ch1], o1);
        if (has2) __stcs(&out[n * HC + ch2], o2);
    }
}

// ---------------- launch ----------------
extern "C" void kernel_launch(void* const* d_in, const int* in_sizes, int n_in,
                              void* d_out, int out_size) {
    const float* x     = (const float*)d_in[0];
    const int*   ei    = (const int*)d_in[1];
    const float* eattr = (const float*)d_in[2];
    const float* W[21];
    for (int i = 0; i < 21; i++) W[i] = (const float*)d_in[3 + i];

    const int* src = ei;
    const int* dst = ei + N_EDGES;

    float* hbuf = nullptr;  cudaGetSymbolAddress((void**)&hbuf, g_h);
    int* counts_ptr = nullptr; cudaGetSymbolAddress((void**)&counts_ptr, g_counts);
    int* done_ptr = nullptr;   cudaGetSymbolAddress((void**)&done_ptr, g_done);

    cudaMemsetAsync(counts_ptr, 0, N_NODES * sizeof(int));
    cudaMemsetAsync(done_ptr, 0, sizeof(int));

    // kernel launch order (ncu captures launch #3): histscan(0), scatter(1), gemm(2), alpha(3)
    k_histscan<<<(N_EDGES + 1023) / 1024, 1024>>>(dst);
    k_scatter <<<(N_EDGES + 255) / 256, 256>>>(src, dst, eattr);

    const float* inp = x;
    int din = F_DIM;
    for (int L = 0; L < 3; L++) {
        const float* wl   = W[L * 7 + 0];
        const float* bl   = W[L * 7 + 1];
        const float* wr   = W[L * 7 + 2];
        const float* br   = W[L * 7 + 3];
        const float* we   = W[L * 7 + 4];
        const float* att  = W[L * 7 + 5];
        const float* bias = W[L * 7 + 6];

        k_gemm<<<(N_NODES + 63) / 64, 256>>>(inp, din, wl, bl, wr, br);

        k_alpha<<<(N_EDGES / 32 + 7) / 8, 256>>>(we, att);

        float* outp = (L == 2) ? (float*)d_out : hbuf;
        k_aggr<<<(N_NODES + 7) / 8, 256>>>(bias, outp, (L < 2) ? 1 : 0);

        inp = hbuf;
        din = HC;
    }
}

// round 10
// speedup vs baseline: 1.3780x; 1.1720x over previous
#include <cuda_runtime.h>
#include <math.h>

#define N_NODES 100000
#define N_EDGES 1000000
#define F_DIM   128
#define ED_DIM  16
#define HC      80

// packed f32x2 FMA (sm_103a FFMA2 — only reachable via PTX)
#define FMA2(d, a, b, c) \
    asm("fma.rn.f32x2 %0, %1, %2, %3;" : "=l"(d) : "l"(a), "l"(b), "l"(c))
#define UNPACK2(lo, hi, v) \
    asm("mov.b64 {%0, %1}, %2;" : "=f"(lo), "=f"(hi) : "l"(v))

// ---------------- scratch (static device globals; no runtime alloc) ----------------
__device__ float g_xl[N_NODES * HC];
__device__ float g_xr[N_NODES * HC];
__device__ float g_h [N_NODES * HC];
__device__ int   g_counts[N_NODES];
__device__ int   g_rowptr[N_NODES + 1];
__device__ int   g_whead [N_NODES];
__device__ int   g_done;
__device__ int   g_csr_src[N_EDGES];
__device__ int   g_csr_dst[N_EDGES];
__device__ float g_eattr_csr[N_EDGES * ED_DIM];   // eattr in CSR slot order
__device__ float g_w[N_EDGES * 5];                // per-edge per-head exp weights

// ---------------- fused hist + exclusive scan (last block scans) ----------------
__global__ void __launch_bounds__(1024) k_histscan(const int* __restrict__ dst) {
    int e = blockIdx.x * 1024 + threadIdx.x;
    if (e < N_EDGES) atomicAdd(&g_counts[__ldcs(&dst[e])], 1);
    __threadfence();
    __shared__ int islast;
    __syncthreads();
    if (threadIdx.x == 0) {
        int t = atomicAdd(&g_done, 1);
        islast = (t == (int)gridDim.x - 1);
    }
    __syncthreads();
    if (!islast) return;

    __shared__ int ssum[1024];
    int tid = threadIdx.x;
    const int per = (N_NODES + 1023) / 1024;
    int base = tid * per;
    int end = base + per; if (end > N_NODES) end = N_NODES;
    int s = 0;
    for (int i = base; i < end; i++) s += g_counts[i];
    ssum[tid] = s;
    __syncthreads();
    for (int d = 1; d < 1024; d <<= 1) {
        int v = (tid >= d) ? ssum[tid - d] : 0;
        __syncthreads();
        ssum[tid] += v;
        __syncthreads();
    }
    int run = (tid > 0) ? ssum[tid - 1] : 0;
    for (int i = base; i < end; i++) {
        g_rowptr[i] = run;
        g_whead[i] = run;
        run += g_counts[i];
    }
    if (tid == 0) g_rowptr[N_NODES] = N_EDGES;
}

// Scatter: csr_src, csr_dst, eattr re-ordered into CSR (dst-sorted) slot order.
__global__ void k_scatter(const int* __restrict__ src, const int* __restrict__ dst,
                          const float* __restrict__ eattr) {
    int e = blockIdx.x * blockDim.x + threadIdx.x;
    if (e < N_EDGES) {
        int d = __ldcs(&dst[e]);
        int p = atomicAdd(&g_whead[d], 1);
        g_csr_src[p] = __ldcs(&src[e]);
        g_csr_dst[p] = d;
        const float4* i4 = reinterpret_cast<const float4*>(eattr) + (size_t)e * 4;
        float4* o4 = reinterpret_cast<float4*>(g_eattr_csr) + (size_t)p * 4;
        float4 v0 = __ldcs(i4 + 0), v1 = __ldcs(i4 + 1);
        float4 v2 = __ldcs(i4 + 2), v3 = __ldcs(i4 + 3);
        __stcs(o4 + 0, v0); __stcs(o4 + 1, v1);
        __stcs(o4 + 2, v2); __stcs(o4 + 3, v3);
    }
}

// ---------------- fused xl/xr GEMM (unchanged) ----------------
__global__ void __launch_bounds__(256) k_gemm(const float* __restrict__ in, int din,
                                              const float* __restrict__ wl, const float* __restrict__ bl,
                                              const float* __restrict__ wr, const float* __restrict__ br) {
    __shared__ float inp_sm[32][65];
    __shared__ float w_sm[32][161];
    int row0 = blockIdx.x * 64;
    int tid = threadIdx.x;
    int ty = tid >> 5;
    int tx = tid & 31;
    float acc[8][5];
#pragma unroll
    for (int r = 0; r < 8; r++)
#pragma unroll
        for (int c = 0; c < 5; c++) acc[r][c] = 0.f;

    for (int kk = 0; kk < din; kk += 32) {
        int kc = din - kk; if (kc > 32) kc = 32;
        for (int i = tid; i < 64 * 32; i += 256) {
            int k = i & 31, r = i >> 5;
            float v = 0.f;
            int row = row0 + r;
            if (k < kc && row < N_NODES) v = __ldcs(&in[row * din + kk + k]);
            inp_sm[k][r] = v;
        }
        for (int i = tid; i < 160 * 32; i += 256) {
            int k = i & 31, c = i >> 5;
            float v = 0.f;
            if (k < kc) v = (c < 80) ? wl[c * din + kk + k] : wr[(c - 80) * din + kk + k];
            w_sm[k][c] = v;
        }
        __syncthreads();
#pragma unroll 8
        for (int k = 0; k < 32; k++) {
            float a[8], b[5];
#pragma unroll
            for (int r = 0; r < 8; r++) a[r] = inp_sm[k][ty * 8 + r];
#pragma unroll
            for (int c = 0; c < 5; c++) b[c] = w_sm[k][tx + 32 * c];
#pragma unroll
            for (int r = 0; r < 8; r++)
#pragma unroll
                for (int c = 0; c < 5; c++) acc[r][c] = fmaf(a[r], b[c], acc[r][c]);
        }
        __syncthreads();
    }
#pragma unroll
    for (int r = 0; r < 8; r++) {
        int row = row0 + ty * 8 + r;
        if (row < N_NODES) {
#pragma unroll
            for (int c = 0; c < 5; c++) {
                int col = tx + 32 * c;
                if (col < 80) g_xl[row * HC + col] = acc[r][c] + bl[col];
                else          __stcs(&g_xr[row * HC + (col - 80)], acc[r][c] + br[col - 80]);
            }
        }
    }
}

// ---------------- phase 1: edge-parallel attention weights ----------------
// R7-proven prefetch structure + FFMA2 packed em + exp predicated to lanes 0/16.
__global__ void __launch_bounds__(256, 2) k_alpha(const float* __restrict__ we,
                                                  const float* __restrict__ att) {
    __shared__ float wsm[8][160];
    int warp = threadIdx.x >> 5;
    int lane = threadIdx.x & 31;
    int base = (blockIdx.x * 8 + warp) * 32;
    if (base >= N_EDGES) return;
    int cnt = N_EDGES - base; if (cnt > 32) cnt = 32;

    int ch0 = lane, ch1 = lane + 32, ch2 = lane + 64;
    bool has2 = lane < 16;
    int ch2c = has2 ? ch2 : 64;

    // We rows as packed f32x2 pairs (8 x 64-bit per row)
    unsigned long long w0p[8], w1p[8], w2p[8];
    const unsigned long long* wq = reinterpret_cast<const unsigned long long*>(we);
#pragma unroll
    for (int t = 0; t < 8; t++) {
        w0p[t] = __ldg(&wq[ch0 * 8 + t]);
        w1p[t] = __ldg(&wq[ch1 * 8 + t]);
        w2p[t] = __ldg(&wq[ch2c * 8 + t]);
    }
    float a0 = __ldg(&att[ch0]), a1 = __ldg(&att[ch1]), a2 = __ldg(&att[ch2c]);

    int sv = 0, dv = 0;
    if (lane < cnt) {
        sv = g_csr_src[base + lane];          // re-read by k_aggr -> keep cached
        dv = __ldcs(&g_csr_dst[base + lane]);
    }

    // prefetch edge 0
    int s0i = __shfl_sync(0xffffffffu, sv, 0);
    int d0i = __shfl_sync(0xffffffffu, dv, 0);
    const float* xp = g_xl + (size_t)s0i * HC;
    const float* rp = g_xr + (size_t)d0i * HC;
    float nx0 = xp[ch0], nx1 = xp[ch1], nx2 = has2 ? xp[ch2] : 0.f;
    float nr0 = rp[ch0], nr1 = rp[ch1], nr2 = has2 ? rp[ch2] : 0.f;
    const longlong2* eap = reinterpret_cast<const longlong2*>(g_eattr_csr + (size_t)base * 16);
    longlong2 nq0 = __ldcs(eap + 0), nq1 = __ldcs(eap + 1);
    longlong2 nq2 = __ldcs(eap + 2), nq3 = __ldcs(eap + 3);

    for (int j = 0; j < cnt; j++) {
        float xs0 = nx0, xs1 = nx1, xs2 = nx2;
        float xr0 = nr0, xr1 = nr1, xr2 = nr2;
        longlong2 q0 = nq0, q1 = nq1, q2 = nq2, q3 = nq3;

        if (j + 1 < cnt) {
            int sn = __shfl_sync(0xffffffffu, sv, j + 1);
            int dn = __shfl_sync(0xffffffffu, dv, j + 1);
            const float* xpn = g_xl + (size_t)sn * HC;
            const float* rpn = g_xr + (size_t)dn * HC;
            nx0 = xpn[ch0]; nx1 = xpn[ch1]; nx2 = has2 ? xpn[ch2] : 0.f;
            nr0 = rpn[ch0]; nr1 = rpn[ch1]; nr2 = has2 ? rpn[ch2] : 0.f;
            const longlong2* ean = reinterpret_cast<const longlong2*>(g_eattr_csr + (size_t)(base + j + 1) * 16);
            nq0 = __ldcs(ean + 0); nq1 = __ldcs(ean + 1);
            nq2 = __ldcs(ean + 2); nq3 = __ldcs(ean + 3);
        }

        // em via packed FFMA2: 24 instructions instead of 48
        unsigned long long qa[8] = {
            (unsigned long long)q0.x, (unsigned long long)q0.y,
            (unsigned long long)q1.x, (unsigned long long)q1.y,
            (unsigned long long)q2.x, (unsigned long long)q2.y,
            (unsigned long long)q3.x, (unsigned long long)q3.y };
        unsigned long long em0p = 0ull, em1p = 0ull, em2p = 0ull;
#pragma unroll
        for (int t = 0; t < 8; t++) {
            FMA2(em0p, w0p[t], qa[t], em0p);
            FMA2(em1p, w1p[t], qa[t], em1p);
            FMA2(em2p, w2p[t], qa[t], em2p);
        }
        float l0, h0, l1, h1, l2, h2;
        UNPACK2(l0, h0, em0p);
        UNPACK2(l1, h1, em1p);
        UNPACK2(l2, h2, em2p);

        float m0 = xs0 + xr0 + (l0 + h0); m0 = (m0 > 0.f) ? m0 : 0.2f * m0;
        float m1 = xs1 + xr1 + (l1 + h1); m1 = (m1 > 0.f) ? m1 : 0.2f * m1;
        float m2 = xs2 + xr2 + (l2 + h2); m2 = (m2 > 0.f) ? m2 : 0.2f * m2;

        float p0 = m0 * a0, p1 = m1 * a1, p2 = m2 * a2;
#pragma unroll
        for (int off = 8; off > 0; off >>= 1) {
            p0 += __shfl_xor_sync(0xffffffffu, p0, off);
            p1 += __shfl_xor_sync(0xffffffffu, p1, off);
            p2 += __shfl_xor_sync(0xffffffffu, p2, off);
        }

        // exp + staging only on the two lanes that own the group results
        if (lane == 0) {
            wsm[warp][j * 5 + 0] = __expf(p0);
            wsm[warp][j * 5 + 2] = __expf(p1);
            wsm[warp][j * 5 + 4] = __expf(p2);
        } else if (lane == 16) {
            wsm[warp][j * 5 + 1] = __expf(p0);
            wsm[warp][j * 5 + 3] = __expf(p1);
        }
    }
    __syncwarp();
    for (int i = lane; i < cnt * 5; i += 32)
        g_w[(size_t)base * 5 + i] = wsm[warp][i];     // default cache: k_aggr re-reads from L2
}

// ---------------- phase 2: per-node weighted aggregation ----------------
__global__ void __launch_bounds__(256) k_aggr(const float* __restrict__ bias,
                                              float* __restrict__ out, int applyRelu) {
    int warp = threadIdx.x >> 5;
    int lane = threadIdx.x & 31;
    int n = blockIdx.x * 8 + warp;
    if (n >= N_NODES) return;

    int ch0 = lane, ch1 = lane + 32, ch2 = lane + 64;
    bool has2 = lane < 16;
    int ch2c = has2 ? ch2 : 64;
    int hsel = lane >> 4;

    float s0 = 0.f, s1 = 0.f, s2 = 0.f;
    float acc0 = 0.f, acc1 = 0.f, acc2 = 0.f;

    int kb = g_rowptr[n], ke = g_rowptr[n + 1];
    for (int cb = kb; cb < ke; cb += 32) {
        int cnt = ke - cb; if (cnt > 32) cnt = 32;
        int sv = 0;
        if (lane < cnt) sv = g_csr_src[cb + lane];

        int src0 = __shfl_sync(0xffffffffu, sv, 0);
        const float* xp = g_xl + (size_t)src0 * HC;
        float nx0 = xp[ch0], nx1 = xp[ch1], nx2 = has2 ? xp[ch2] : 0.f;
        const float* wp = g_w + (size_t)cb * 5;
        float nw0 = wp[hsel];
        float nw1 = wp[2 + hsel];
        float nw2 = wp[4];

        for (int j = 0; j < cnt; j++) {
            float xs0 = nx0, xs1 = nx1, xs2 = nx2;
            float wv0 = nw0, wv1 = nw1, wv2 = nw2;
            if (j + 1 < cnt) {
                int sn = __shfl_sync(0xffffffffu, sv, j + 1);
                const float* xpn = g_xl + (size_t)sn * HC;
                nx0 = xpn[ch0]; nx1 = xpn[ch1]; nx2 = has2 ? xpn[ch2] : 0.f;
                const float* wpn = g_w + (size_t)(cb + j + 1) * 5;
                nw0 = wpn[hsel];
                nw1 = wpn[2 + hsel];
                nw2 = wpn[4];
            }
            s0 += wv0; acc0 = fmaf(wv0, xs0, acc0);
            s1 += wv1; acc1 = fmaf(wv1, xs1, acc1);
            s2 += wv2; acc2 = fmaf(wv2, xs2, acc2);
        }
    }

    float o0 = acc0 / (s0 + 1e-16f) + __ldg(&bias[ch0]);
    float o1 = acc1 / (s1 + 1e-16f) + __ldg(&bias[ch1]);
    float o2 = acc2 / (s2 + 1e-16f) + __ldg(&bias[ch2c]);
    if (applyRelu) {
        out[n * HC + ch0] = fmaxf(o0, 0.f);
        out[n * HC + ch1] = fmaxf(o1, 0.f);
        if (has2) out[n * HC + ch2] = fmaxf(o2, 0.f);
    } else {
        __stcs(&out[n * HC + ch0], o0);
        __stcs(&out[n * HC + ch1], o1);
        if (has2) __stcs(&out[n * HC + ch2], o2);
    }
}

// ---------------- launch ----------------
extern "C" void kernel_launch(void* const* d_in, const int* in_sizes, int n_in,
                              void* d_out, int out_size) {
    const float* x     = (const float*)d_in[0];
    const int*   ei    = (const int*)d_in[1];
    const float* eattr = (const float*)d_in[2];
    const float* W[21];
    for (int i = 0; i < 21; i++) W[i] = (const float*)d_in[3 + i];

    const int* src = ei;
    const int* dst = ei + N_EDGES;

    float* hbuf = nullptr;  cudaGetSymbolAddress((void**)&hbuf, g_h);
    int* counts_ptr = nullptr; cudaGetSymbolAddress((void**)&counts_ptr, g_counts);
    int* done_ptr = nullptr;   cudaGetSymbolAddress((void**)&done_ptr, g_done);

    cudaMemsetAsync(counts_ptr, 0, N_NODES * sizeof(int));
    cudaMemsetAsync(done_ptr, 0, sizeof(int));

    // kernel launch order (ncu captures launch #3): histscan(0), scatter(1), gemm(2), alpha(3)
    k_histscan<<<(N_EDGES + 1023) / 1024, 1024>>>(dst);
    k_scatter <<<(N_EDGES + 255) / 256, 256>>>(src, dst, eattr);

    const float* inp = x;
    int din = F_DIM;
    for (int L = 0; L < 3; L++) {
        const float* wl   = W[L * 7 + 0];
        const float* bl   = W[L * 7 + 1];
        const float* wr   = W[L * 7 + 2];
        const float* br   = W[L * 7 + 3];
        const float* we   = W[L * 7 + 4];
        const float* att  = W[L * 7 + 5];
        const float* bias = W[L * 7 + 6];

        k_gemm<<<(N_NODES + 63) / 64, 256>>>(inp, din, wl, bl, wr, br);

        k_alpha<<<(N_EDGES / 32 + 7) / 8, 256>>>(we, att);

        float* outp = (L == 2) ? (float*)d_out : hbuf;
        k_aggr<<<(N_NODES + 7) / 8, 256>>>(bias, outp, (L < 2) ? 1 : 0);

        inp = hbuf;
        din = HC;
    }
}